// round 10
// baseline (speedup 1.0000x reference)
#include <cuda_runtime.h>
#include <cuda_fp16.h>
#include <cstdint>
#include <math.h>

#define BATCH    4096
#define IN_DIM   512
#define NEURONS  1024
#define OUT_DIM  512
#define NBASIS   18

// ---------------------------------------------------------------------------
// Scratch (allocation-free rule: device globals)
// ---------------------------------------------------------------------------
__device__ __align__(256) float  g_h    [BATCH * NEURONS];      // 16 MB
__device__ __align__(256) __half g_x_h  [BATCH * IN_DIM];       // A1 (fp16)
__device__ __align__(256) __half g_w1_hi[NEURONS * IN_DIM];     // B1 hi [N,K]
__device__ __align__(256) __half g_w1_lo[NEURONS * IN_DIM];     // B1 lo [N,K]
__device__ __align__(256) __half g_w2_h [OUT_DIM * NEURONS];    // B2 [N,K] (single fp16)
__device__ __align__(256) __half g_sp_h [BATCH * NEURONS];      // A2 (fp16)

// ---------------------------------------------------------------------------
// PTX helpers (sm_80+ subset: cp.async, ldmatrix, mma.sync)
// ---------------------------------------------------------------------------
__device__ __forceinline__ uint32_t smem_u32(const void* p) {
    uint32_t a;
    asm("{ .reg .u64 t; cvta.to.shared.u64 t, %1; cvt.u32.u64 %0, t; }" : "=r"(a) : "l"(p));
    return a;
}
#define CP16(dst, src) \
    asm volatile("cp.async.cg.shared.global [%0], [%1], 16;" :: "r"(dst), "l"(src) : "memory")
#define CP_COMMIT() asm volatile("cp.async.commit_group;" ::: "memory")
#define CP_WAIT1()  asm volatile("cp.async.wait_group 1;" ::: "memory")
#define CP_WAIT2()  asm volatile("cp.async.wait_group 2;" ::: "memory")

#define LDM4(r, addr)                                                        \
    asm volatile("ldmatrix.sync.aligned.m8n8.x4.shared.b16 {%0,%1,%2,%3}, [%4];" \
        : "=r"((r)[0]), "=r"((r)[1]), "=r"((r)[2]), "=r"((r)[3]) : "r"(addr))

#define MMA_F16(c, a, b0, b1)                                                \
    asm volatile("mma.sync.aligned.m16n8k16.row.col.f32.f16.f16.f32 "        \
        "{%0,%1,%2,%3},{%4,%5,%6,%7},{%8,%9},{%0,%1,%2,%3};"                 \
        : "+f"((c)[0]), "+f"((c)[1]), "+f"((c)[2]), "+f"((c)[3])             \
        : "r"((a)[0]), "r"((a)[1]), "r"((a)[2]), "r"((a)[3]), "r"(b0), "r"(b1))

// ---------------------------------------------------------------------------
// Conversion helpers
// ---------------------------------------------------------------------------
__device__ __forceinline__ void split2h(float v, __half& hi, __half& lo) {
    hi = __float2half_rn(v);
    lo = __float2half_rn(v - __half2float(hi));
}

// One 32x32 transpose+split tile (coalesced both sides).
__device__ __forceinline__ void tsplit_tile(
    const float* __restrict__ src, __half* __restrict__ hi,
    __half* __restrict__ lo, int R, int C, int c0, int r0, int tid)
{
    __shared__ float t[32][33];
    const int tx = tid & 31;
    const int ty = tid >> 5;
    #pragma unroll
    for (int j = ty; j < 32; j += 8)
        t[j][tx] = src[(size_t)(r0 + j) * C + c0 + tx];
    __syncthreads();
    #pragma unroll
    for (int j = ty; j < 32; j += 8) {
        __half h, l;
        split2h(t[tx][j], h, l);
        const size_t o = (size_t)(c0 + j) * R + r0 + tx;
        hi[o] = h;
        if (lo) lo[o] = l;
    }
}

// Single merged prologue kernel:
//   blocks [0, 2048):     x fp32 -> fp16           (4 elems/thread)
//   blocks [2048, 2560):  W1 transpose+split tiles (512 tiles)
//   blocks [2560, 3072):  W2 transpose (single fp16) tiles (512 tiles)
__global__ __launch_bounds__(256) void conv_all_kernel(
    const float* __restrict__ x, const float* __restrict__ W1,
    const float* __restrict__ W2)
{
    const int b   = blockIdx.x;
    const int tid = threadIdx.x;
    if (b < 2048) {
        const int i = (b * 256 + tid) * 4;
        const float4 v = *(const float4*)(x + i);
        *(__half2*)(g_x_h + i)     = __floats2half2_rn(v.x, v.y);
        *(__half2*)(g_x_h + i + 2) = __floats2half2_rn(v.z, v.w);
    } else if (b < 2560) {
        const int t = b - 2048;                 // W1: R=512, C=1024
        tsplit_tile(W1, g_w1_hi, g_w1_lo, IN_DIM, NEURONS,
                    (t & 31) * 32, (t >> 5) * 32, tid);
    } else {
        const int t = b - 2560;                 // W2: R=1024, C=512
        tsplit_tile(W2, g_w2_h, (__half*)0, NEURONS, OUT_DIM,
                    (t & 15) * 32, (t >> 4) * 32, tid);
    }
}

// ---------------------------------------------------------------------------
// Common GEMM geometry: CTA tile 128(M) x 64(N), 8 warps 4(M)x2(N),
// warp tile 32x32, BK=64.
// ---------------------------------------------------------------------------
#define BK          64
#define ROWB        144                   // 64 fp16 = 128B + 16B pad
#define TA          (128 * ROWB)          // A tile  18432 B
#define TB          (64  * ROWB)          // B tile   9216 B
// 2-pass variant: 3 stages of (A, Bhi, Blo)
#define STAGE2B     (TA + 2 * TB)         // 36864 B
#define GEMM2P_SMEM (3 * STAGE2B)         // 110592 B -> 2 CTAs/SM
// 1-pass variant: 4 stages of (A, B)
#define STAGE1B     (TA + TB)             // 27648 B
#define GEMM1P_SMEM (4 * STAGE1B)         // 110592 B -> 2 CTAs/SM

// ---------------------------------------------------------------------------
// 2-pass fp16-split GEMM (A fp16; B hi+lo): C = A @ B^T + bias
// 3-stage pipeline, issue-before-compute, wait_group 1.
// ---------------------------------------------------------------------------
__global__ __launch_bounds__(256, 2) void gemm_mma2_kernel(
    const __half* __restrict__ A, const __half* __restrict__ Bhi,
    const __half* __restrict__ Blo,
    const float* __restrict__ bias, float* __restrict__ C,
    int K, int Ntot, int relu)
{
    extern __shared__ char smem[];
    const uint32_t sb = smem_u32(smem);
    const int tid  = threadIdx.x;
    const int wid  = tid >> 5;
    const int lane = tid & 31;
    const int warp_m = wid & 3;
    const int warp_n = wid >> 2;
    const int m0 = blockIdx.y * 128;
    const int n0 = blockIdx.x * 64;

    const __half* aG  = A   + (size_t)m0 * K;
    const __half* bhG = Bhi + (size_t)n0 * K;
    const __half* blG = Blo + (size_t)n0 * K;

    float acc[2][4][4];
    #pragma unroll
    for (int i = 0; i < 2; i++)
        #pragma unroll
        for (int j = 0; j < 4; j++)
            #pragma unroll
            for (int q = 0; q < 4; q++) acc[i][j][q] = 0.0f;

    const int NC = K / BK;

    auto issue = [&](int c, int s) {
        if (c < NC) {
            const int kc = c * BK;
            const uint32_t st = sb + s * STAGE2B;
            #pragma unroll
            for (int i = 0; i < 8; i++) {
                const int id = tid + i * 256;          // 0..2047
                const int seg = id & 7;
                const __half* src;
                uint32_t dst;
                if (id < 1024) {                       // A rows 0..127
                    const int row = id >> 3;
                    src = aG + (size_t)row * K + kc + seg * 8;
                    dst = st + row * ROWB + seg * 16;
                } else if (id < 1536) {                // Bhi rows 0..63
                    const int row = (id - 1024) >> 3;
                    src = bhG + (size_t)row * K + kc + seg * 8;
                    dst = st + TA + row * ROWB + seg * 16;
                } else {                               // Blo rows 0..63
                    const int row = (id - 1536) >> 3;
                    src = blG + (size_t)row * K + kc + seg * 8;
                    dst = st + TA + TB + row * ROWB + seg * 16;
                }
                CP16(dst, src);
            }
        }
        CP_COMMIT();
    };

    issue(0, 0);
    issue(1, 1);

    const int a_row = ((lane >> 3) & 1) * 8 + (lane & 7);
    const int a_kb  = ((lane >> 4) & 1) * 16;
    const int b_nad = ((lane >> 4) & 1) * 8 + (lane & 7);
    const int b_kb  = ((lane >> 3) & 1) * 16;

    for (int c = 0; c < NC; c++) {
        const int s = c % 3;
        CP_WAIT1();
        __syncthreads();
        issue(c + 2, (c + 2) % 3);

        const uint32_t stage = sb + s * STAGE2B;
        const uint32_t aB   = stage + (warp_m * 32 + a_row) * ROWB + a_kb;
        const uint32_t bHiB = stage + TA      + (warp_n * 32 + b_nad) * ROWB + b_kb;
        const uint32_t bLoB = stage + TA + TB + (warp_n * 32 + b_nad) * ROWB + b_kb;

        #pragma unroll
        for (int ks = 0; ks < 4; ks++) {
            const uint32_t ko = ks * 32;
            uint32_t af[2][4], bh[2][4], bl[2][4];
            LDM4(af[0], aB + ko);
            LDM4(af[1], aB + 16 * ROWB + ko);
            #pragma unroll
            for (int fn = 0; fn < 2; fn++) {
                LDM4(bh[fn], bHiB + fn * 16 * ROWB + ko);
                LDM4(bl[fn], bLoB + fn * 16 * ROWB + ko);
            }
            #pragma unroll
            for (int fm = 0; fm < 2; fm++) {
                #pragma unroll
                for (int f = 0; f < 4; f++) {
                    const int fn = f >> 1;
                    const int h  = f & 1;
                    MMA_F16(acc[fm][f], af[fm], bh[fn][h * 2], bh[fn][h * 2 + 1]);
                    MMA_F16(acc[fm][f], af[fm], bl[fn][h * 2], bl[fn][h * 2 + 1]);
                }
            }
        }
    }

    const int gr = lane >> 2;
    const int tq = lane & 3;
    #pragma unroll
    for (int fm = 0; fm < 2; fm++) {
        const int r0 = m0 + warp_m * 32 + fm * 16 + gr;
        #pragma unroll
        for (int f = 0; f < 4; f++) {
            const int col = n0 + warp_n * 32 + f * 8 + tq * 2;
            const float bx = bias[col], by = bias[col + 1];
            float v0 = acc[fm][f][0] + bx;
            float v1 = acc[fm][f][1] + by;
            float v2 = acc[fm][f][2] + bx;
            float v3 = acc[fm][f][3] + by;
            if (relu) {
                v0 = fmaxf(v0, 0.0f); v1 = fmaxf(v1, 0.0f);
                v2 = fmaxf(v2, 0.0f); v3 = fmaxf(v3, 0.0f);
            }
            *(float2*)(C + (size_t)r0 * Ntot + col)       = make_float2(v0, v1);
            *(float2*)(C + (size_t)(r0 + 8) * Ntot + col) = make_float2(v2, v3);
        }
    }
}

// ---------------------------------------------------------------------------
// 1-pass fp16 GEMM (A fp16; B fp16): C = A @ B^T + bias (opt relu)
// 4-stage pipeline, issue-before-compute, wait_group 2 (prefetch depth 2).
// ---------------------------------------------------------------------------
__global__ __launch_bounds__(256, 2) void gemm_mma1_kernel(
    const __half* __restrict__ A, const __half* __restrict__ B,
    const float* __restrict__ bias, float* __restrict__ C,
    int K, int Ntot, int relu)
{
    extern __shared__ char smem[];
    const uint32_t sb = smem_u32(smem);
    const int tid  = threadIdx.x;
    const int wid  = tid >> 5;
    const int lane = tid & 31;
    const int warp_m = wid & 3;
    const int warp_n = wid >> 2;
    const int m0 = blockIdx.y * 128;
    const int n0 = blockIdx.x * 64;

    const __half* aG = A + (size_t)m0 * K;
    const __half* bG = B + (size_t)n0 * K;

    float acc[2][4][4];
    #pragma unroll
    for (int i = 0; i < 2; i++)
        #pragma unroll
        for (int j = 0; j < 4; j++)
            #pragma unroll
            for (int q = 0; q < 4; q++) acc[i][j][q] = 0.0f;

    const int NC = K / BK;

    // Load one stage: A 1024 + B 512 = 1536 x 16B chunks, 6 per thread.
    auto issue = [&](int c, int s) {
        if (c < NC) {
            const int kc = c * BK;
            const uint32_t st = sb + s * STAGE1B;
            #pragma unroll
            for (int i = 0; i < 6; i++) {
                const int id = tid + i * 256;          // 0..1535
                const int seg = id & 7;
                const __half* src;
                uint32_t dst;
                if (id < 1024) {                       // A rows 0..127
                    const int row = id >> 3;
                    src = aG + (size_t)row * K + kc + seg * 8;
                    dst = st + row * ROWB + seg * 16;
                } else {                               // B rows 0..63
                    const int row = (id - 1024) >> 3;
                    src = bG + (size_t)row * K + kc + seg * 8;
                    dst = st + TA + row * ROWB + seg * 16;
                }
                CP16(dst, src);
            }
        }
        CP_COMMIT();
    };

    issue(0, 0);
    issue(1, 1);
    issue(2, 2);

    const int a_row = ((lane >> 3) & 1) * 8 + (lane & 7);
    const int a_kb  = ((lane >> 4) & 1) * 16;
    const int b_nad = ((lane >> 4) & 1) * 8 + (lane & 7);
    const int b_kb  = ((lane >> 3) & 1) * 16;

    for (int c = 0; c < NC; c++) {
        const int s = c & 3;
        CP_WAIT2();
        __syncthreads();
        // Slot (c+3)&3 == (c-1)&3 was finished last iteration; the barrier
        // above guarantees all warps are done reading it.
        issue(c + 3, (c + 3) & 3);

        const uint32_t stage = sb + s * STAGE1B;
        const uint32_t aB = stage + (warp_m * 32 + a_row) * ROWB + a_kb;
        const uint32_t bB = stage + TA + (warp_n * 32 + b_nad) * ROWB + b_kb;

        #pragma unroll
        for (int ks = 0; ks < 4; ks++) {
            const uint32_t ko = ks * 32;
            uint32_t af[2][4], bf[2][4];
            LDM4(af[0], aB + ko);
            LDM4(af[1], aB + 16 * ROWB + ko);
            LDM4(bf[0], bB + ko);
            LDM4(bf[1], bB + 16 * ROWB + ko);
            #pragma unroll
            for (int fm = 0; fm < 2; fm++) {
                #pragma unroll
                for (int f = 0; f < 4; f++) {
                    const int fn = f >> 1;
                    const int h  = f & 1;
                    MMA_F16(acc[fm][f], af[fm], bf[fn][h * 2], bf[fn][h * 2 + 1]);
                }
            }
        }
    }

    const int gr = lane >> 2;
    const int tq = lane & 3;
    #pragma unroll
    for (int fm = 0; fm < 2; fm++) {
        const int r0 = m0 + warp_m * 32 + fm * 16 + gr;
        #pragma unroll
        for (int f = 0; f < 4; f++) {
            const int col = n0 + warp_n * 32 + f * 8 + tq * 2;
            const float bx = bias[col], by = bias[col + 1];
            float v0 = acc[fm][f][0] + bx;
            float v1 = acc[fm][f][1] + by;
            float v2 = acc[fm][f][2] + bx;
            float v3 = acc[fm][f][3] + by;
            if (relu) {
                v0 = fmaxf(v0, 0.0f); v1 = fmaxf(v1, 0.0f);
                v2 = fmaxf(v2, 0.0f); v3 = fmaxf(v3, 0.0f);
            }
            *(float2*)(C + (size_t)r0 * Ntot + col)       = make_float2(v0, v1);
            *(float2*)(C + (size_t)(r0 + 8) * Ntot + col) = make_float2(v2, v3);
        }
    }
}

// ---------------------------------------------------------------------------
// Fused row min-max norm + uniform cubic B-spline; writes fp16 sp.
// 2 rows per block: threads [0,128) -> row 2b, [128,256) -> row 2b+1.
// Each thread handles 8 elements. Min/max reductions are exact (order-free).
// ---------------------------------------------------------------------------
__global__ __launch_bounds__(256) void spline_kernel(
    const float* __restrict__ coeff, const float* __restrict__ sp_bias)
{
    __shared__ float s_mn[2][4], s_mx[2][4];

    const int half = threadIdx.x >> 7;          // 0 or 1
    const int wt   = threadIdx.x & 127;         // thread within row
    const int row  = blockIdx.x * 2 + half;
    const float* hr = g_h + (size_t)row * NEURONS;

    float v[8];
    *(float4*)(v)     = *(const float4*)(hr + wt * 8);
    *(float4*)(v + 4) = *(const float4*)(hr + wt * 8 + 4);

    float mn = v[0], mx = v[0];
    #pragma unroll
    for (int i = 1; i < 8; i++) {
        mn = fminf(mn, v[i]);
        mx = fmaxf(mx, v[i]);
    }
    #pragma unroll
    for (int off = 16; off > 0; off >>= 1) {
        mn = fminf(mn, __shfl_xor_sync(0xFFFFFFFFu, mn, off));
        mx = fmaxf(mx, __shfl_xor_sync(0xFFFFFFFFu, mx, off));
    }
    if ((wt & 31) == 0) { s_mn[half][wt >> 5] = mn; s_mx[half][wt >> 5] = mx; }
    __syncthreads();
    mn = s_mn[half][0]; mx = s_mx[half][0];
    #pragma unroll
    for (int w = 1; w < 4; w++) {
        mn = fminf(mn, s_mn[half][w]);
        mx = fmaxf(mx, s_mx[half][w]);
    }

    const float inv = 1.0f / (mx - mn + 1e-8f);

    __half2 res[4];
    #pragma unroll
    for (int i = 0; i < 8; i += 2) {
        float rr[2];
        #pragma unroll
        for (int q = 0; q < 2; q++) {
            const int n = wt * 8 + i + q;
            const float u = (v[i + q] - mn) * inv;
            float t = u * 15.0f;
            int m = (int)floorf(t);
            m = max(0, min(m, 15));
            const float s  = t - (float)m;
            const float s2 = s * s;
            const float s3 = s2 * s;
            const float os = 1.0f - s;
            const float w0 = (1.0f / 6.0f) * os * os * os;
            const float w1 = (1.0f / 6.0f) * (3.0f * s3 - 6.0f * s2 + 4.0f);
            const float w2 = (1.0f / 6.0f) * (-3.0f * s3 + 3.0f * s2 + 3.0f * s + 1.0f);
            const float w3 = (1.0f / 6.0f) * s3;

            const float* cf = coeff + n * NBASIS + m;
            float r = w0 * cf[0] + w1 * cf[1] + w2 * cf[2];
            const int i3 = min(m + 3, NBASIS - 1);
            r += w3 * coeff[n * NBASIS + i3];
            rr[q] = r + sp_bias[n];
        }
        res[i >> 1] = __floats2half2_rn(rr[0], rr[1]);
    }
    *(uint4*)(g_sp_h + (size_t)row * NEURONS + wt * 8) = *(uint4*)res;
}

// ---------------------------------------------------------------------------
extern "C" void kernel_launch(void* const* d_in, const int* in_sizes, int n_in,
                              void* d_out, int out_size)
{
    const float* x       = (const float*)d_in[0];   // [4096, 512]
    const float* W1      = (const float*)d_in[1];   // [512, 1024]
    const float* b1      = (const float*)d_in[2];   // [1024]
    const float* coeff   = (const float*)d_in[3];   // [1024, 18]
    const float* sp_bias = (const float*)d_in[4];   // [1024]
    const float* W2      = (const float*)d_in[5];   // [1024, 512]
    const float* b2      = (const float*)d_in[6];   // [512]
    float*       out     = (float*)d_out;           // [4096, 512]

    float *h_ptr = nullptr;
    __half *xh, *w1h, *w1l, *w2h, *sph;
    cudaGetSymbolAddress((void**)&h_ptr, g_h);
    cudaGetSymbolAddress((void**)&xh,  g_x_h);
    cudaGetSymbolAddress((void**)&w1h, g_w1_hi); cudaGetSymbolAddress((void**)&w1l, g_w1_lo);
    cudaGetSymbolAddress((void**)&w2h, g_w2_h);
    cudaGetSymbolAddress((void**)&sph, g_sp_h);

    cudaFuncSetAttribute(gemm_mma2_kernel,
                         cudaFuncAttributeMaxDynamicSharedMemorySize, GEMM2P_SMEM);
    cudaFuncSetAttribute(gemm_mma1_kernel,
                         cudaFuncAttributeMaxDynamicSharedMemorySize, GEMM1P_SMEM);

    // Merged prologue: x -> fp16; W1 -> transposed hi/lo; W2 -> transposed fp16
    conv_all_kernel<<<3072, 256>>>(x, W1, W2);

    // GEMM1 (2-pass): h = x @ W1 + b1   [4096,1024]
    {
        dim3 grid(NEURONS / 64, BATCH / 128);
        gemm_mma2_kernel<<<grid, 256, GEMM2P_SMEM>>>(xh, w1h, w1l, b1, h_ptr,
                                                     IN_DIM, NEURONS, 0);
    }
    // norm + spline -> fp16 sp (2 rows per block)
    spline_kernel<<<BATCH / 2, 256>>>(coeff, sp_bias);

    // GEMM2 (1-pass, 4-stage): out = relu(sp @ W2 + b2)  [4096,512]
    {
        dim3 grid(OUT_DIM / 64, BATCH / 128);
        gemm_mma1_kernel<<<grid, 256, GEMM1P_SMEM>>>(sph, w2h, b2, out,
                                                     NEURONS, OUT_DIM, 1);
    }
}

// round 11
// speedup vs baseline: 1.0483x; 1.0483x over previous
#include <cuda_runtime.h>
#include <cuda_fp16.h>
#include <cstdint>
#include <math.h>

#define BATCH    4096
#define IN_DIM   512
#define NEURONS  1024
#define OUT_DIM  512
#define NBASIS   18

// ---------------------------------------------------------------------------
// Scratch (allocation-free rule: device globals)
// ---------------------------------------------------------------------------
__device__ __align__(256) float  g_h    [BATCH * NEURONS];      // 16 MB
__device__ __align__(256) __half g_x_h  [BATCH * IN_DIM];       // A1 (fp16)
__device__ __align__(256) __half g_w1_hi[NEURONS * IN_DIM];     // B1 hi [N,K]
__device__ __align__(256) __half g_w1_lo[NEURONS * IN_DIM];     // B1 lo [N,K]
__device__ __align__(256) __half g_w2_h [OUT_DIM * NEURONS];    // B2 [N,K] (single fp16)
__device__ __align__(256) __half g_sp_h [BATCH * NEURONS];      // A2 (fp16)

// ---------------------------------------------------------------------------
// PTX helpers (sm_80+ subset: cp.async, ldmatrix, mma.sync)
// ---------------------------------------------------------------------------
__device__ __forceinline__ uint32_t smem_u32(const void* p) {
    uint32_t a;
    asm("{ .reg .u64 t; cvta.to.shared.u64 t, %1; cvt.u32.u64 %0, t; }" : "=r"(a) : "l"(p));
    return a;
}
#define CP16(dst, src) \
    asm volatile("cp.async.cg.shared.global [%0], [%1], 16;" :: "r"(dst), "l"(src) : "memory")
#define CP_COMMIT() asm volatile("cp.async.commit_group;" ::: "memory")
#define CP_WAIT1()  asm volatile("cp.async.wait_group 1;" ::: "memory")

#define LDM4(r, addr)                                                        \
    asm volatile("ldmatrix.sync.aligned.m8n8.x4.shared.b16 {%0,%1,%2,%3}, [%4];" \
        : "=r"((r)[0]), "=r"((r)[1]), "=r"((r)[2]), "=r"((r)[3]) : "r"(addr))

#define MMA_F16(c, a, b0, b1)                                                \
    asm volatile("mma.sync.aligned.m16n8k16.row.col.f32.f16.f16.f32 "        \
        "{%0,%1,%2,%3},{%4,%5,%6,%7},{%8,%9},{%0,%1,%2,%3};"                 \
        : "+f"((c)[0]), "+f"((c)[1]), "+f"((c)[2]), "+f"((c)[3])             \
        : "r"((a)[0]), "r"((a)[1]), "r"((a)[2]), "r"((a)[3]), "r"(b0), "r"(b1))

// ---------------------------------------------------------------------------
// Conversion helpers
// ---------------------------------------------------------------------------
__device__ __forceinline__ void split2h(float v, __half& hi, __half& lo) {
    hi = __float2half_rn(v);
    lo = __float2half_rn(v - __half2float(hi));
}

// One 32x32 transpose+split tile (coalesced both sides).
__device__ __forceinline__ void tsplit_tile(
    const float* __restrict__ src, __half* __restrict__ hi,
    __half* __restrict__ lo, int R, int C, int c0, int r0, int tid)
{
    __shared__ float t[32][33];
    const int tx = tid & 31;
    const int ty = tid >> 5;
    #pragma unroll
    for (int j = ty; j < 32; j += 8)
        t[j][tx] = src[(size_t)(r0 + j) * C + c0 + tx];
    __syncthreads();
    #pragma unroll
    for (int j = ty; j < 32; j += 8) {
        __half h, l;
        split2h(t[tx][j], h, l);
        const size_t o = (size_t)(c0 + j) * R + r0 + tx;
        hi[o] = h;
        if (lo) lo[o] = l;
    }
}

// Single merged prologue kernel:
//   blocks [0, 2048):     x fp32 -> fp16           (4 elems/thread)
//   blocks [2048, 2560):  W1 transpose+split tiles (512 tiles)
//   blocks [2560, 3072):  W2 transpose (single fp16) tiles (512 tiles)
__global__ __launch_bounds__(256) void conv_all_kernel(
    const float* __restrict__ x, const float* __restrict__ W1,
    const float* __restrict__ W2)
{
    const int b   = blockIdx.x;
    const int tid = threadIdx.x;
    if (b < 2048) {
        const int i = (b * 256 + tid) * 4;
        const float4 v = *(const float4*)(x + i);
        *(__half2*)(g_x_h + i)     = __floats2half2_rn(v.x, v.y);
        *(__half2*)(g_x_h + i + 2) = __floats2half2_rn(v.z, v.w);
    } else if (b < 2560) {
        const int t = b - 2048;                 // W1: R=512, C=1024
        tsplit_tile(W1, g_w1_hi, g_w1_lo, IN_DIM, NEURONS,
                    (t & 31) * 32, (t >> 5) * 32, tid);
    } else {
        const int t = b - 2560;                 // W2: R=1024, C=512
        tsplit_tile(W2, g_w2_h, (__half*)0, NEURONS, OUT_DIM,
                    (t & 15) * 32, (t >> 4) * 32, tid);
    }
}

// ---------------------------------------------------------------------------
// Common GEMM geometry
// ---------------------------------------------------------------------------
#define BK          64
#define ROWB        144                   // 64 fp16 = 128B + 16B pad
#define TA          (128 * ROWB)          // A tile  18432 B
#define TB          (64  * ROWB)          // B tile   9216 B
// 2-pass variant: 3 stages of (A, Bhi, Blo)
#define STAGE2B     (TA + 2 * TB)         // 36864 B
#define GEMM2P_SMEM (3 * STAGE2B)         // 110592 B -> 2 CTAs/SM
// 1-pass variant: 3 stages of (A, B)
#define STAGE1B     (TA + TB)             // 27648 B
#define GEMM1P_SMEM (3 * STAGE1B)         // 82944 B -> 2 CTAs/SM

// ---------------------------------------------------------------------------
// 2-pass fp16-split GEMM (A fp16; B hi+lo): C = A @ B^T + bias
// CTA 128x64, 8 warps 4(M)x2(N), warp 32x32, 3-stage pipeline. (unchanged R9)
// ---------------------------------------------------------------------------
__global__ __launch_bounds__(256, 2) void gemm_mma2_kernel(
    const __half* __restrict__ A, const __half* __restrict__ Bhi,
    const __half* __restrict__ Blo,
    const float* __restrict__ bias, float* __restrict__ C,
    int K, int Ntot, int relu)
{
    extern __shared__ char smem[];
    const uint32_t sb = smem_u32(smem);
    const int tid  = threadIdx.x;
    const int wid  = tid >> 5;
    const int lane = tid & 31;
    const int warp_m = wid & 3;
    const int warp_n = wid >> 2;
    const int m0 = blockIdx.y * 128;
    const int n0 = blockIdx.x * 64;

    const __half* aG  = A   + (size_t)m0 * K;
    const __half* bhG = Bhi + (size_t)n0 * K;
    const __half* blG = Blo + (size_t)n0 * K;

    float acc[2][4][4];
    #pragma unroll
    for (int i = 0; i < 2; i++)
        #pragma unroll
        for (int j = 0; j < 4; j++)
            #pragma unroll
            for (int q = 0; q < 4; q++) acc[i][j][q] = 0.0f;

    const int NC = K / BK;

    auto issue = [&](int c, int s) {
        if (c < NC) {
            const int kc = c * BK;
            const uint32_t st = sb + s * STAGE2B;
            #pragma unroll
            for (int i = 0; i < 8; i++) {
                const int id = tid + i * 256;          // 0..2047
                const int seg = id & 7;
                const __half* src;
                uint32_t dst;
                if (id < 1024) {                       // A rows 0..127
                    const int row = id >> 3;
                    src = aG + (size_t)row * K + kc + seg * 8;
                    dst = st + row * ROWB + seg * 16;
                } else if (id < 1536) {                // Bhi rows 0..63
                    const int row = (id - 1024) >> 3;
                    src = bhG + (size_t)row * K + kc + seg * 8;
                    dst = st + TA + row * ROWB + seg * 16;
                } else {                               // Blo rows 0..63
                    const int row = (id - 1536) >> 3;
                    src = blG + (size_t)row * K + kc + seg * 8;
                    dst = st + TA + TB + row * ROWB + seg * 16;
                }
                CP16(dst, src);
            }
        }
        CP_COMMIT();
    };

    issue(0, 0);
    issue(1, 1);

    const int a_row = ((lane >> 3) & 1) * 8 + (lane & 7);
    const int a_kb  = ((lane >> 4) & 1) * 16;
    const int b_nad = ((lane >> 4) & 1) * 8 + (lane & 7);
    const int b_kb  = ((lane >> 3) & 1) * 16;

    for (int c = 0; c < NC; c++) {
        const int s = c % 3;
        CP_WAIT1();
        __syncthreads();
        issue(c + 2, (c + 2) % 3);

        const uint32_t stage = sb + s * STAGE2B;
        const uint32_t aB   = stage + (warp_m * 32 + a_row) * ROWB + a_kb;
        const uint32_t bHiB = stage + TA      + (warp_n * 32 + b_nad) * ROWB + b_kb;
        const uint32_t bLoB = stage + TA + TB + (warp_n * 32 + b_nad) * ROWB + b_kb;

        #pragma unroll
        for (int ks = 0; ks < 4; ks++) {
            const uint32_t ko = ks * 32;
            uint32_t af[2][4], bh[2][4], bl[2][4];
            LDM4(af[0], aB + ko);
            LDM4(af[1], aB + 16 * ROWB + ko);
            #pragma unroll
            for (int fn = 0; fn < 2; fn++) {
                LDM4(bh[fn], bHiB + fn * 16 * ROWB + ko);
                LDM4(bl[fn], bLoB + fn * 16 * ROWB + ko);
            }
            #pragma unroll
            for (int fm = 0; fm < 2; fm++) {
                #pragma unroll
                for (int f = 0; f < 4; f++) {
                    const int fn = f >> 1;
                    const int h  = f & 1;
                    MMA_F16(acc[fm][f], af[fm], bh[fn][h * 2], bh[fn][h * 2 + 1]);
                    MMA_F16(acc[fm][f], af[fm], bl[fn][h * 2], bl[fn][h * 2 + 1]);
                }
            }
        }
    }

    const int gr = lane >> 2;
    const int tq = lane & 3;
    #pragma unroll
    for (int fm = 0; fm < 2; fm++) {
        const int r0 = m0 + warp_m * 32 + fm * 16 + gr;
        #pragma unroll
        for (int f = 0; f < 4; f++) {
            const int col = n0 + warp_n * 32 + f * 8 + tq * 2;
            const float bx = bias[col], by = bias[col + 1];
            float v0 = acc[fm][f][0] + bx;
            float v1 = acc[fm][f][1] + by;
            float v2 = acc[fm][f][2] + bx;
            float v3 = acc[fm][f][3] + by;
            if (relu) {
                v0 = fmaxf(v0, 0.0f); v1 = fmaxf(v1, 0.0f);
                v2 = fmaxf(v2, 0.0f); v3 = fmaxf(v3, 0.0f);
            }
            *(float2*)(C + (size_t)r0 * Ntot + col)       = make_float2(v0, v1);
            *(float2*)(C + (size_t)(r0 + 8) * Ntot + col) = make_float2(v2, v3);
        }
    }
}

// ---------------------------------------------------------------------------
// 1-pass fp16 GEMM (A fp16; B fp16): C = A @ B^T + bias (opt relu)
// CTA 128x64, 4 warps (warp_m = wid), warp tile 32x64 (full N width):
// per ks-step 6 LDSM -> 16 MMA (25% fewer LDSM than 32x32 tiles).
// 3-stage pipeline, issue-before-compute, 128 threads, 2 CTAs/SM.
// ---------------------------------------------------------------------------
__global__ __launch_bounds__(128, 2) void gemm_mma1_kernel(
    const __half* __restrict__ A, const __half* __restrict__ B,
    const float* __restrict__ bias, float* __restrict__ C,
    int K, int Ntot, int relu)
{
    extern __shared__ char smem[];
    const uint32_t sb = smem_u32(smem);
    const int tid  = threadIdx.x;
    const int warp_m = tid >> 5;          // 0..3
    const int lane = tid & 31;
    const int m0 = blockIdx.y * 128;
    const int n0 = blockIdx.x * 64;

    const __half* aG = A + (size_t)m0 * K;
    const __half* bG = B + (size_t)n0 * K;

    float acc[2][8][4];                   // fm x (fn*2+h) x quad
    #pragma unroll
    for (int i = 0; i < 2; i++)
        #pragma unroll
        for (int j = 0; j < 8; j++)
            #pragma unroll
            for (int q = 0; q < 4; q++) acc[i][j][q] = 0.0f;

    const int NC = K / BK;

    // Load one stage: A 1024 + B 512 = 1536 x 16B chunks, 12 per thread.
    auto issue = [&](int c, int s) {
        if (c < NC) {
            const int kc = c * BK;
            const uint32_t st = sb + s * STAGE1B;
            #pragma unroll
            for (int i = 0; i < 12; i++) {
                const int id = tid + i * 128;          // 0..1535
                const int seg = id & 7;
                const __half* src;
                uint32_t dst;
                if (id < 1024) {                       // A rows 0..127
                    const int row = id >> 3;
                    src = aG + (size_t)row * K + kc + seg * 8;
                    dst = st + row * ROWB + seg * 16;
                } else {                               // B rows 0..63
                    const int row = (id - 1024) >> 3;
                    src = bG + (size_t)row * K + kc + seg * 8;
                    dst = st + TA + row * ROWB + seg * 16;
                }
                CP16(dst, src);
            }
        }
        CP_COMMIT();
    };

    issue(0, 0);
    issue(1, 1);

    const int a_row = ((lane >> 3) & 1) * 8 + (lane & 7);
    const int a_kb  = ((lane >> 4) & 1) * 16;
    const int b_nad = ((lane >> 4) & 1) * 8 + (lane & 7);
    const int b_kb  = ((lane >> 3) & 1) * 16;

    for (int c = 0; c < NC; c++) {
        const int s = c % 3;
        CP_WAIT1();
        __syncthreads();
        issue(c + 2, (c + 2) % 3);

        const uint32_t stage = sb + s * STAGE1B;
        const uint32_t aB = stage + (warp_m * 32 + a_row) * ROWB + a_kb;
        const uint32_t bB = stage + TA + b_nad * ROWB + b_kb;   // all 64 B-rows

        #pragma unroll
        for (int ks = 0; ks < 4; ks++) {
            const uint32_t ko = ks * 32;
            uint32_t af[2][4], bf[4][4];
            LDM4(af[0], aB + ko);
            LDM4(af[1], aB + 16 * ROWB + ko);
            #pragma unroll
            for (int fn = 0; fn < 4; fn++)
                LDM4(bf[fn], bB + fn * 16 * ROWB + ko);
            #pragma unroll
            for (int fm = 0; fm < 2; fm++) {
                #pragma unroll
                for (int f = 0; f < 8; f++) {
                    const int fn = f >> 1;
                    const int h  = f & 1;
                    MMA_F16(acc[fm][f], af[fm], bf[fn][h * 2], bf[fn][h * 2 + 1]);
                }
            }
        }
    }

    const int gr = lane >> 2;
    const int tq = lane & 3;
    #pragma unroll
    for (int fm = 0; fm < 2; fm++) {
        const int r0 = m0 + warp_m * 32 + fm * 16 + gr;
        #pragma unroll
        for (int f = 0; f < 8; f++) {
            const int col = n0 + f * 8 + tq * 2;
            const float bx = bias[col], by = bias[col + 1];
            float v0 = acc[fm][f][0] + bx;
            float v1 = acc[fm][f][1] + by;
            float v2 = acc[fm][f][2] + bx;
            float v3 = acc[fm][f][3] + by;
            if (relu) {
                v0 = fmaxf(v0, 0.0f); v1 = fmaxf(v1, 0.0f);
                v2 = fmaxf(v2, 0.0f); v3 = fmaxf(v3, 0.0f);
            }
            *(float2*)(C + (size_t)r0 * Ntot + col)       = make_float2(v0, v1);
            *(float2*)(C + (size_t)(r0 + 8) * Ntot + col) = make_float2(v2, v3);
        }
    }
}

// ---------------------------------------------------------------------------
// Fused row min-max norm + uniform cubic B-spline; writes fp16 sp. (R9 form)
// ---------------------------------------------------------------------------
__global__ __launch_bounds__(256) void spline_kernel(
    const float* __restrict__ coeff, const float* __restrict__ sp_bias)
{
    __shared__ float s_mn[8], s_mx[8];

    const int row = blockIdx.x;
    const int tid = threadIdx.x;
    const float* hr = g_h + (size_t)row * NEURONS;

    const float4 v4 = *(const float4*)(hr + tid * 4);
    float v[4] = { v4.x, v4.y, v4.z, v4.w };
    float mn = fminf(fminf(v[0], v[1]), fminf(v[2], v[3]));
    float mx = fmaxf(fmaxf(v[0], v[1]), fmaxf(v[2], v[3]));

    #pragma unroll
    for (int off = 16; off > 0; off >>= 1) {
        mn = fminf(mn, __shfl_xor_sync(0xFFFFFFFFu, mn, off));
        mx = fmaxf(mx, __shfl_xor_sync(0xFFFFFFFFu, mx, off));
    }
    if ((tid & 31) == 0) { s_mn[tid >> 5] = mn; s_mx[tid >> 5] = mx; }
    __syncthreads();
    mn = s_mn[0]; mx = s_mx[0];
    #pragma unroll
    for (int w = 1; w < 8; w++) { mn = fminf(mn, s_mn[w]); mx = fmaxf(mx, s_mx[w]); }

    const float inv = 1.0f / (mx - mn + 1e-8f);

    float r[4];
    #pragma unroll
    for (int i = 0; i < 4; i++) {
        const int n = tid * 4 + i;
        const float u = (v[i] - mn) * inv;
        float t = u * 15.0f;
        int m = (int)floorf(t);
        m = max(0, min(m, 15));
        const float s  = t - (float)m;
        const float s2 = s * s;
        const float s3 = s2 * s;
        const float os = 1.0f - s;
        const float w0 = (1.0f / 6.0f) * os * os * os;
        const float w1 = (1.0f / 6.0f) * (3.0f * s3 - 6.0f * s2 + 4.0f);
        const float w2 = (1.0f / 6.0f) * (-3.0f * s3 + 3.0f * s2 + 3.0f * s + 1.0f);
        const float w3 = (1.0f / 6.0f) * s3;

        const float* cf = coeff + n * NBASIS + m;
        float rr = w0 * cf[0] + w1 * cf[1] + w2 * cf[2];
        const int i3 = min(m + 3, NBASIS - 1);
        rr += w3 * coeff[n * NBASIS + i3];
        r[i] = rr + sp_bias[n];
    }
    const size_t o = (size_t)row * NEURONS + tid * 4;
    *(__half2*)(g_sp_h + o)     = __floats2half2_rn(r[0], r[1]);
    *(__half2*)(g_sp_h + o + 2) = __floats2half2_rn(r[2], r[3]);
}

// ---------------------------------------------------------------------------
extern "C" void kernel_launch(void* const* d_in, const int* in_sizes, int n_in,
                              void* d_out, int out_size)
{
    const float* x       = (const float*)d_in[0];   // [4096, 512]
    const float* W1      = (const float*)d_in[1];   // [512, 1024]
    const float* b1      = (const float*)d_in[2];   // [1024]
    const float* coeff   = (const float*)d_in[3];   // [1024, 18]
    const float* sp_bias = (const float*)d_in[4];   // [1024]
    const float* W2      = (const float*)d_in[5];   // [1024, 512]
    const float* b2      = (const float*)d_in[6];   // [512]
    float*       out     = (float*)d_out;           // [4096, 512]

    float *h_ptr = nullptr;
    __half *xh, *w1h, *w1l, *w2h, *sph;
    cudaGetSymbolAddress((void**)&h_ptr, g_h);
    cudaGetSymbolAddress((void**)&xh,  g_x_h);
    cudaGetSymbolAddress((void**)&w1h, g_w1_hi); cudaGetSymbolAddress((void**)&w1l, g_w1_lo);
    cudaGetSymbolAddress((void**)&w2h, g_w2_h);
    cudaGetSymbolAddress((void**)&sph, g_sp_h);

    cudaFuncSetAttribute(gemm_mma2_kernel,
                         cudaFuncAttributeMaxDynamicSharedMemorySize, GEMM2P_SMEM);
    cudaFuncSetAttribute(gemm_mma1_kernel,
                         cudaFuncAttributeMaxDynamicSharedMemorySize, GEMM1P_SMEM);

    // Merged prologue: x -> fp16; W1 -> transposed hi/lo; W2 -> transposed fp16
    conv_all_kernel<<<3072, 256>>>(x, W1, W2);

    // GEMM1 (2-pass): h = x @ W1 + b1   [4096,1024]
    {
        dim3 grid(NEURONS / 64, BATCH / 128);
        gemm_mma2_kernel<<<grid, 256, GEMM2P_SMEM>>>(xh, w1h, w1l, b1, h_ptr,
                                                     IN_DIM, NEURONS, 0);
    }
    // norm + spline -> fp16 sp
    spline_kernel<<<BATCH, 256>>>(coeff, sp_bias);

    // GEMM2 (1-pass, wide warp tiles): out = relu(sp @ W2 + b2)  [4096,512]
    {
        dim3 grid(OUT_DIM / 64, BATCH / 128);
        gemm_mma1_kernel<<<grid, 128, GEMM1P_SMEM>>>(sph, w2h, b2, out,
                                                     NEURONS, OUT_DIM, 1);
    }
}